// round 7
// baseline (speedup 1.0000x reference)
#include <cuda_runtime.h>
#include <cuda_bf16.h>
#include <cstdint>

#define MAX_SEG 16384
#define PAD 8            // one float counter per 32B L2 sector

// Padded scatter accumulators (track/hit separated; zero-init at load;
// corr_kernel self-cleans them after reading).
__device__ float g_track[MAX_SEG * PAD];
__device__ float g_hit[MAX_SEG * PAD];

// Packed table for the gather phase: ONE 16B read per hit.
//   x = e_track_raw  y = e_track_corr  z = e_hit_raw  w = e_hit_corr
__device__ float4 g_shower[MAX_SEG];

// ---------------------------------------------------------------------------
// TMA-fed scatter: tiles of T_TILE hits are bulk-copied (sid/energy/rid) into
// double-buffered smem by ONE thread per tile (TMA unit, no per-lane LSU
// wavefronts); all 256 threads then consume via LDS.128 and spend the LSU
// exclusively on REDGs. __syncthreads() at loop end is the buffer-free
// backpressure; mbarrier complete_tx (acquire wait) orders TMA vs LDS.
// ---------------------------------------------------------------------------
#define T_TILE   1024
#define SC_TPB   256
#define SEG_BYTES (T_TILE * 4)          // 4096B per field per tile

__device__ __forceinline__ uint32_t smem_u32(const void* p) {
    uint32_t a;
    asm("{ .reg .u64 t; cvta.to.shared.u64 t, %1; cvt.u32.u64 %0, t; }"
        : "=r"(a) : "l"(p));
    return a;
}

__device__ __forceinline__ void mbar_init(uint32_t mbar, uint32_t cnt) {
    asm volatile("mbarrier.init.shared.b64 [%0], %1;" :: "r"(mbar), "r"(cnt)
                 : "memory");
}
__device__ __forceinline__ void mbar_expect_tx(uint32_t mbar, uint32_t bytes) {
    asm volatile("mbarrier.arrive.expect_tx.shared.b64 _, [%0], %1;"
                 :: "r"(mbar), "r"(bytes) : "memory");
}
__device__ __forceinline__ void mbar_wait(uint32_t mbar, uint32_t parity) {
    uint32_t done;
    asm volatile(
        "{\n\t.reg .pred p;\n\t"
        "mbarrier.try_wait.parity.acquire.cta.shared::cta.b64 p, [%1], %2;\n\t"
        "selp.b32 %0, 1, 0, p;\n\t}"
        : "=r"(done) : "r"(mbar), "r"(parity) : "memory");
    if (!done) {
        asm volatile(
            "{\n\t.reg .pred P1;\n\t"
            "W_%=:\n\t"
            "mbarrier.try_wait.parity.acquire.cta.shared::cta.b64 P1, [%0], %1, 0x989680;\n\t"
            "@P1 bra.uni D_%=;\n\t"
            "bra.uni W_%=;\n\t"
            "D_%=:\n\t}"
            :: "r"(mbar), "r"(parity) : "memory");
    }
}
__device__ __forceinline__ void tma_bulk_g2s(uint32_t dst, const void* src,
                                             uint32_t bytes, uint32_t mbar) {
    asm volatile(
        "cp.async.bulk.shared::cluster.global.mbarrier::complete_tx::bytes "
        "[%0], [%1], %2, [%3];"
        :: "r"(dst), "l"(src), "r"(bytes), "r"(mbar) : "memory");
}

__global__ void __launch_bounds__(SC_TPB) scatter_tma_kernel(
        const int* __restrict__ sid,
        const float* __restrict__ energy,
        const int* __restrict__ rid,
        long ntiles) {
    // Double-buffered tile storage: [buf][field][T_TILE*4 bytes]
    __shared__ __align__(128) char sm[2][3 * SEG_BYTES];
    __shared__ __align__(8) unsigned long long mbar_s[2];

    int tid = threadIdx.x;
    uint32_t mbar[2] = { smem_u32(&mbar_s[0]), smem_u32(&mbar_s[1]) };
    uint32_t buf[2]  = { smem_u32(&sm[0][0]),  smem_u32(&sm[1][0]) };

    if (tid == 0) { mbar_init(mbar[0], 1); mbar_init(mbar[1], 1); }
    __syncthreads();

    long g0 = blockIdx.x;
    // Prologue: issue first tile
    if (g0 < ntiles && tid == 0) {
        long base = g0 * T_TILE;
        mbar_expect_tx(mbar[0], 3 * SEG_BYTES);
        tma_bulk_g2s(buf[0],                sid    + base, SEG_BYTES, mbar[0]);
        tma_bulk_g2s(buf[0] +   SEG_BYTES,  energy + base, SEG_BYTES, mbar[0]);
        tma_bulk_g2s(buf[0] + 2*SEG_BYTES,  rid    + base, SEG_BYTES, mbar[0]);
    }

    int local = 0;
    for (long g = g0; g < ntiles; g += gridDim.x, local++) {
        int cur = local & 1;
        uint32_t parity = (local >> 1) & 1;
        mbar_wait(mbar[cur], parity);

        // Issue next tile into the other buffer (free since the previous
        // iteration's __syncthreads).
        long gn = g + gridDim.x;
        if (gn < ntiles && tid == 0) {
            int nx = cur ^ 1;
            long base = gn * T_TILE;
            mbar_expect_tx(mbar[nx], 3 * SEG_BYTES);
            tma_bulk_g2s(buf[nx],               sid    + base, SEG_BYTES, mbar[nx]);
            tma_bulk_g2s(buf[nx] +   SEG_BYTES, energy + base, SEG_BYTES, mbar[nx]);
            tma_bulk_g2s(buf[nx] + 2*SEG_BYTES, rid    + base, SEG_BYTES, mbar[nx]);
        }

        // Consume 4 hits per thread from smem (conflict-free LDS.128).
        const char* b = &sm[cur][0];
        int4   s4 = ((const int4*)  (b))[tid];
        float4 e4 = ((const float4*)(b + SEG_BYTES))[tid];
        int4   r4 = ((const int4*)  (b + 2*SEG_BYTES))[tid];
        int   s[4] = {s4.x, s4.y, s4.z, s4.w};
        float e[4] = {e4.x, e4.y, e4.z, e4.w};
        int   r[4] = {r4.x, r4.y, r4.z, r4.w};
#pragma unroll
        for (int k = 0; k < 4; k++) {
            if (s[k] >= 0) {
                float* p = (r[k] == 1) ? &g_track[(s[k] + 1) * PAD]
                                       : &g_hit[(s[k] + 1) * PAD];
                atomicAdd(p, e[k]);
            }
        }
        __syncthreads();   // buffer-free backpressure for the producer
    }
}

// Remainder (n % T_TILE hits) — tiny scalar pass.
__global__ void scatter_rem_kernel(const int* __restrict__ sid,
                                   const float* __restrict__ energy,
                                   const int* __restrict__ rid,
                                   long start, long n) {
    long i = start + blockIdx.x * blockDim.x + threadIdx.x;
    if (i >= n) return;
    int sv = sid[i];
    if (sv >= 0) {
        float* p = (rid[i] == 1) ? &g_track[(sv + 1) * PAD]
                                 : &g_hit[(sv + 1) * PAD];
        atomicAdd(p, energy[i]);
    }
}

// ---------------------------------------------------------------------------
// Correction + repack + self-clean.
// corr[s] (s>=1) = pcf_ext[alpha_idx[s-1]], pcf_ext[j] = pcf[j] if j < n_hits
// and sid[j] != -1, else 0. corr[0] = 0.
// ---------------------------------------------------------------------------
__global__ void corr_kernel(const int* __restrict__ sid,
                            const float* __restrict__ pcf,
                            const int* __restrict__ a_tracks,
                            const int* __restrict__ a_hits,
                            int n_hits, int nseg) {
    int s = blockIdx.x * blockDim.x + threadIdx.x;
    if (s >= nseg) return;
    float ct = 0.f, ch = 0.f;
    if (s > 0) {
        int jt = a_tracks[s - 1];
        if (jt >= 0 && jt < n_hits && __ldg(sid + jt) != -1) ct = __ldg(pcf + jt);
        int jh = a_hits[s - 1];
        if (jh >= 0 && jh < n_hits && __ldg(sid + jh) != -1) ch = __ldg(pcf + jh);
    }
    float et = g_track[s * PAD];
    float eh = g_hit[s * PAD];
    g_shower[s] = make_float4(et, et * ct, eh, eh * ch);
    g_track[s * PAD] = 0.f;   // clean for the next launch
    g_hit[s * PAD]   = 0.f;
}

// ---------------------------------------------------------------------------
// Gather — 4 hits/thread (best measured form): 1 int4 sid load ->
// 4 independent random 16B table reads -> 4 coalesced float4 stores.
//   [0,n) e_track_raw [n,2n) e_track_corr [2n,3n) e_hit_raw [3n,4n) e_hit_corr
// ---------------------------------------------------------------------------
__global__ void __launch_bounds__(256) gather_kernel_vec(
        const int* __restrict__ sid,
        float* __restrict__ out,
        int n) {
    int t = blockIdx.x * blockDim.x + threadIdx.x;
    if ((long)t * 4 >= n) return;
    int4 s4 = __ldg((const int4*)(sid) + t);
    float4 v0 = g_shower[s4.x + 1];
    float4 v1 = g_shower[s4.y + 1];
    float4 v2 = g_shower[s4.z + 1];
    float4 v3 = g_shower[s4.w + 1];
    float4* o0 = (float4*)(out)          + t;
    float4* o1 = (float4*)(out + n)      + t;
    float4* o2 = (float4*)(out + 2ll*n)  + t;
    float4* o3 = (float4*)(out + 3ll*n)  + t;
    *o0 = make_float4(v0.x, v1.x, v2.x, v3.x);
    *o1 = make_float4(v0.y, v1.y, v2.y, v3.y);
    *o2 = make_float4(v0.z, v1.z, v2.z, v3.z);
    *o3 = make_float4(v0.w, v1.w, v2.w, v3.w);
}

__global__ void gather_kernel_scalar(const int* __restrict__ sid,
                                     float* __restrict__ out,
                                     int n) {
    int i = blockIdx.x * blockDim.x + threadIdx.x;
    if (i >= n) return;
    float4 v = g_shower[__ldg(sid + i) + 1];
    out[i]          = v.x;
    out[i + 1ll*n]  = v.y;
    out[i + 2ll*n]  = v.z;
    out[i + 3ll*n]  = v.w;
}

extern "C" void kernel_launch(void* const* d_in, const int* in_sizes, int n_in,
                              void* d_out, int out_size) {
    const int*   pred_sid = (const int*)  d_in[0];
    const float* pcf      = (const float*)d_in[1];
    const float* energy   = (const float*)d_in[2];
    const int*   rid      = (const int*)  d_in[3];
    // d_in[4] = pred_beta (unused)
    const int*   a_tracks = (const int*)  d_in[5];
    const int*   a_hits   = (const int*)  d_in[6];
    float*       out      = (float*)d_out;

    int n_hits    = in_sizes[0];
    int n_showers = in_sizes[5];
    int nseg      = n_showers + 1;
    if (nseg > MAX_SEG) nseg = MAX_SEG;

    static int sm_count = 0;
    if (sm_count == 0) {
        cudaDeviceProp prop;
        cudaGetDeviceProperties(&prop, 0);
        sm_count = prop.multiProcessorCount;
        if (sm_count <= 0) sm_count = 148;
    }

    const int TPB = 256;

    long ntiles = (long)n_hits / T_TILE;
    long rem_start = ntiles * T_TILE;

    if (ntiles > 0) {
        long grid = 4L * sm_count;          // 4 CTAs/SM (smem: 4 x 26KB)
        if (grid > ntiles) grid = ntiles;
        scatter_tma_kernel<<<(unsigned)grid, SC_TPB>>>(pred_sid, energy, rid,
                                                       ntiles);
    }
    if (rem_start < n_hits) {
        long rem = n_hits - rem_start;
        scatter_rem_kernel<<<(unsigned)((rem + TPB - 1) / TPB), TPB>>>(
            pred_sid, energy, rid, rem_start, n_hits);
    }

    corr_kernel<<<(nseg + TPB - 1) / TPB, TPB>>>(pred_sid, pcf, a_tracks, a_hits,
                                                 n_hits, nseg);

    if ((n_hits & 3) == 0) {
        int n4 = n_hits / 4;
        gather_kernel_vec<<<(n4 + TPB - 1) / TPB, TPB>>>(pred_sid, out, n_hits);
    } else {
        gather_kernel_scalar<<<(n_hits + TPB - 1) / TPB, TPB>>>(pred_sid, out,
                                                                n_hits);
    }
}

// round 8
// speedup vs baseline: 1.1879x; 1.1879x over previous
#include <cuda_runtime.h>
#include <cuda_bf16.h>

#define MAX_SEG 16384
#define PAD 8   // one float counter per 32B L2 sector

// Padded scatter accumulators: track/hit in separate arrays, one counter per
// 32B sector (no two hot atomics share an L2 sector). Zero-initialized at
// module load; corr_kernel self-cleans after reading, so every launch starts
// from a clean state without a dedicated zeroing kernel.
__device__ float g_track[MAX_SEG * PAD];
__device__ float g_hit[MAX_SEG * PAD];

// Packed table for the gather phase: ONE 16B read per hit.
//   x = e_track_raw  y = e_track_corr  z = e_hit_raw  w = e_hit_corr
__device__ float4 g_shower[MAX_SEG];

__device__ __forceinline__ void stcs_f4(float4* p, float4 v) {
    asm volatile("st.global.cs.v4.f32 [%0], {%1,%2,%3,%4};"
                 :: "l"(p), "f"(v.x), "f"(v.y), "f"(v.z), "f"(v.w)
                 : "memory");
}

// ---------------------------------------------------------------------------
// Kernel 1: scatter — segment-sum energies into padded per-shower counters.
// 8 hits per thread, loads front-batched, then 8 predicated global REDs
// (fire-and-forget; kernel is REDG-wavefront-drain bound).
// Noise hits (sid == -1) contribute exactly 0 in the reference -> skipped.
// recHitID==1 -> track, ==0 -> hit.
// ---------------------------------------------------------------------------
__global__ void __launch_bounds__(256) scatter8_kernel(
        const int* __restrict__ sid,
        const float* __restrict__ energy,
        const int* __restrict__ rid,
        int n) {
    int t = blockIdx.x * blockDim.x + threadIdx.x;
    long base = (long)t * 8;
    if (base + 8 <= n) {
        int4   s0 = __ldg((const int4*)(sid)      + 2*t);
        int4   s1 = __ldg((const int4*)(sid)      + 2*t + 1);
        float4 e0 = __ldg((const float4*)(energy) + 2*t);
        float4 e1 = __ldg((const float4*)(energy) + 2*t + 1);
        int4   r0 = __ldg((const int4*)(rid)      + 2*t);
        int4   r1 = __ldg((const int4*)(rid)      + 2*t + 1);
        int   s[8] = {s0.x, s0.y, s0.z, s0.w, s1.x, s1.y, s1.z, s1.w};
        float e[8] = {e0.x, e0.y, e0.z, e0.w, e1.x, e1.y, e1.z, e1.w};
        int   r[8] = {r0.x, r0.y, r0.z, r0.w, r1.x, r1.y, r1.z, r1.w};
#pragma unroll
        for (int k = 0; k < 8; k++) {
            if (s[k] >= 0) {
                float* p = (r[k] == 1) ? &g_track[(s[k] + 1) * PAD]
                                       : &g_hit[(s[k] + 1) * PAD];
                atomicAdd(p, e[k]);
            }
        }
    } else if (base < n) {
        for (long i = base; i < n; i++) {
            int sv = sid[i];
            if (sv >= 0) {
                float* p = (rid[i] == 1) ? &g_track[(sv + 1) * PAD]
                                         : &g_hit[(sv + 1) * PAD];
                atomicAdd(p, energy[i]);
            }
        }
    }
}

// ---------------------------------------------------------------------------
// Kernel 2: per-shower correction + repack into the float4 table + self-clean.
// corr[s] (s>=1) = pcf_ext[alpha_idx[s-1]], pcf_ext[j] = pcf[j] if j < n_hits
// and sid[j] != -1, else 0. corr[0] = 0.
// ---------------------------------------------------------------------------
__global__ void corr_kernel(const int* __restrict__ sid,
                            const float* __restrict__ pcf,
                            const int* __restrict__ a_tracks,
                            const int* __restrict__ a_hits,
                            int n_hits, int nseg) {
    int s = blockIdx.x * blockDim.x + threadIdx.x;
    if (s >= nseg) return;
    float ct = 0.f, ch = 0.f;
    if (s > 0) {
        int jt = a_tracks[s - 1];
        if (jt >= 0 && jt < n_hits && __ldg(sid + jt) != -1) ct = __ldg(pcf + jt);
        int jh = a_hits[s - 1];
        if (jh >= 0 && jh < n_hits && __ldg(sid + jh) != -1) ch = __ldg(pcf + jh);
    }
    float et = g_track[s * PAD];
    float eh = g_hit[s * PAD];
    g_shower[s] = make_float4(et, et * ct, eh, eh * ch);
    g_track[s * PAD] = 0.f;   // clean for the next launch
    g_hit[s * PAD]   = 0.f;
}

// ---------------------------------------------------------------------------
// Kernel 3: gather — 4 hits/thread: 1 int4 sid load -> 4 independent random
// 16B table reads (L2-resident table) -> 4 coalesced float4 STREAMING stores
// (output is never re-read; evict-first preserves L2 for sid/table across
// graph replays). Output layout (reference tuple order):
//   [0,n) e_track_raw [n,2n) e_track_corr [2n,3n) e_hit_raw [3n,4n) e_hit_corr
// ---------------------------------------------------------------------------
__global__ void __launch_bounds__(256) gather_kernel_vec(
        const int* __restrict__ sid,
        float* __restrict__ out,
        int n) {
    int t = blockIdx.x * blockDim.x + threadIdx.x;
    if ((long)t * 4 >= n) return;
    int4 s4 = __ldg((const int4*)(sid) + t);
    float4 v0 = g_shower[s4.x + 1];
    float4 v1 = g_shower[s4.y + 1];
    float4 v2 = g_shower[s4.z + 1];
    float4 v3 = g_shower[s4.w + 1];
    stcs_f4((float4*)(out)         + t, make_float4(v0.x, v1.x, v2.x, v3.x));
    stcs_f4((float4*)(out + n)     + t, make_float4(v0.y, v1.y, v2.y, v3.y));
    stcs_f4((float4*)(out + 2ll*n) + t, make_float4(v0.z, v1.z, v2.z, v3.z));
    stcs_f4((float4*)(out + 3ll*n) + t, make_float4(v0.w, v1.w, v2.w, v3.w));
}

__global__ void gather_kernel_scalar(const int* __restrict__ sid,
                                     float* __restrict__ out,
                                     int n) {
    int i = blockIdx.x * blockDim.x + threadIdx.x;
    if (i >= n) return;
    float4 v = g_shower[__ldg(sid + i) + 1];
    out[i]          = v.x;
    out[i + 1ll*n]  = v.y;
    out[i + 2ll*n]  = v.z;
    out[i + 3ll*n]  = v.w;
}

extern "C" void kernel_launch(void* const* d_in, const int* in_sizes, int n_in,
                              void* d_out, int out_size) {
    const int*   pred_sid = (const int*)  d_in[0];
    const float* pcf      = (const float*)d_in[1];
    const float* energy   = (const float*)d_in[2];
    const int*   rid      = (const int*)  d_in[3];
    // d_in[4] = pred_beta (unused)
    const int*   a_tracks = (const int*)  d_in[5];
    const int*   a_hits   = (const int*)  d_in[6];
    float*       out      = (float*)d_out;

    int n_hits    = in_sizes[0];
    int n_showers = in_sizes[5];
    int nseg      = n_showers + 1;
    if (nseg > MAX_SEG) nseg = MAX_SEG;

    const int TPB = 256;

    int n8 = (n_hits + 7) / 8;
    scatter8_kernel<<<(n8 + TPB - 1) / TPB, TPB>>>(pred_sid, energy, rid, n_hits);

    corr_kernel<<<(nseg + TPB - 1) / TPB, TPB>>>(pred_sid, pcf, a_tracks, a_hits,
                                                 n_hits, nseg);

    if ((n_hits & 3) == 0) {
        int n4 = n_hits / 4;
        gather_kernel_vec<<<(n4 + TPB - 1) / TPB, TPB>>>(pred_sid, out, n_hits);
    } else {
        gather_kernel_scalar<<<(n_hits + TPB - 1) / TPB, TPB>>>(pred_sid, out,
                                                                n_hits);
    }
}